// round 2
// baseline (speedup 1.0000x reference)
#include <cuda_runtime.h>
#include <math.h>

#define NTOK 32768
#define NH 8
#define HD 24
#define HDIM 28
#define NSEG 48
#define CHUNK 4096

// ---------- scratch (device globals; no runtime allocation) ----------
static __device__ float g_qkv[(size_t)NTOK * 576];                 // [n][q(192)|k(192)|v(192)]
static __device__ float g_qhat[(size_t)NH * NTOK * HDIM];          // [h][n][28]
static __device__ float g_khat[(size_t)NH * NTOK * HDIM];
static __device__ unsigned long long g_keys[(size_t)NSEG * NTOK];  // seg 0..23 = q(r,h), 24..47 = k(r,h)
static __device__ float g_o[(size_t)24 * NTOK * HD];               // [r*8+h][n][24] scattered to orig n
static __device__ float g_z[(size_t)24 * NTOK];                    // logsumexp, scattered
static __device__ float g_w[16];                                   // w[h][c]
static __device__ float g_wsq[16];                                 // sqrt(2*w)

__device__ __forceinline__ unsigned ford(float f) {
    unsigned u = __float_as_uint(f);
    return (u & 0x80000000u) ? ~u : (u | 0x80000000u);
}

// ---------- RPE weights ----------
__global__ void k_w(const float* __restrict__ W) {
    int t = threadIdx.x;
    if (t < 16) {
        int h = t >> 1, c = t & 1;
        float s = 0.f;
        for (int i = 0; i < 24; i++)
            for (int j = 0; j < 8; j++)
                s += W[(h * 24 + i) * 16 + c * 8 + j];
        s *= (1.f / 192.f);
        float w = s * s;
        g_w[t] = w;
        g_wsq[t] = sqrtf(2.f * w);
    }
}

// ---------- LayerNorm1 + QKV GEMM ----------
__global__ void __launch_bounds__(256) k_ln_qkv(
    const float* __restrict__ x, const float* __restrict__ g1, const float* __restrict__ b1,
    const float* __restrict__ Wq, const float* __restrict__ Wk, const float* __restrict__ Wv) {
    __shared__ float xn[32][25];
    int base = blockIdx.x * 32;
    int tid = threadIdx.x;
    if (tid < 32) {
        int row = base + tid;
        float xv[24];
        float mu = 0.f;
        #pragma unroll
        for (int i = 0; i < 24; i++) { xv[i] = x[(size_t)row * 24 + i]; mu += xv[i]; }
        mu *= (1.f / 24.f);
        float var = 0.f;
        #pragma unroll
        for (int i = 0; i < 24; i++) { float d = xv[i] - mu; var += d * d; }
        var *= (1.f / 24.f);
        float inv = rsqrtf(var + 1e-5f);
        #pragma unroll
        for (int i = 0; i < 24; i++) xn[tid][i] = (xv[i] - mu) * inv * g1[i] + b1[i];
    }
    __syncthreads();
    for (int idx = tid; idx < 32 * 576; idx += 256) {
        int row = idx / 576;
        int col = idx - row * 576;
        const float* W = (col < 192) ? Wq : ((col < 384) ? Wk : Wv);
        int cc = (col < 192) ? col : ((col < 384) ? col - 192 : col - 384);
        float a = 0.f;
        #pragma unroll
        for (int i = 0; i < 24; i++) a = fmaf(xn[row][i], W[i * 192 + cc], a);
        g_qkv[(size_t)(base + row) * 576 + col] = a;
    }
}

// ---------- build q_hat / k_hat + hash sort keys ----------
__global__ void __launch_bounds__(256) k_build(const float* __restrict__ coords,
                                               const float* __restrict__ alphas) {
    int idx = blockIdx.x * 256 + threadIdx.x;
    int h = idx & 7;
    int n = idx >> 3;
    float p0 = coords[n * 3 + 1], p1 = coords[n * 3 + 2];
    float sqn = g_w[h * 2] * p0 * p0 + g_w[h * 2 + 1] * p1 * p1;
    float qp0 = g_wsq[h * 2] * p0, qp1 = g_wsq[h * 2 + 1] * p1;
    float qh[HDIM], kh[HDIM];
    const float* qkv = &g_qkv[(size_t)n * 576];
    const float qscale = 0.2041241452319315f;  // 1/sqrt(24)
    #pragma unroll
    for (int i = 0; i < 24; i++) { qh[i] = qkv[h * 24 + i] * qscale; kh[i] = qkv[192 + h * 24 + i]; }
    qh[24] = qp0; qh[25] = qp1; qh[26] = -sqn; qh[27] = 1.f;
    kh[24] = qp0; kh[25] = qp1; kh[26] = 1.f;  kh[27] = -sqn;
    float* qd = &g_qhat[((size_t)h * NTOK + n) * HDIM];
    float* kd = &g_khat[((size_t)h * NTOK + n) * HDIM];
    #pragma unroll
    for (int i = 0; i < HDIM; i++) { qd[i] = qh[i]; kd[i] = kh[i]; }
    #pragma unroll
    for (int r = 0; r < 3; r++) {
        const float* a = &alphas[(r * 8 + h) * HDIM];
        float sq = 0.f, sk = 0.f;
        #pragma unroll
        for (int i = 0; i < HDIM; i++) { sq = fmaf(qh[i], a[i], sq); sk = fmaf(kh[i], a[i], sk); }
        g_keys[(size_t)(r * 8 + h) * NTOK + n] = ((unsigned long long)ford(sq) << 32) | (unsigned)n;
        g_keys[(size_t)(24 + r * 8 + h) * NTOK + n] = ((unsigned long long)ford(sk) << 32) | (unsigned)n;
    }
}

// ---------- bitonic sort: chunk presort (stages k=2..4096) ----------
__global__ void __launch_bounds__(512) k_presort() {
    __shared__ unsigned long long s[CHUNK];
    int seg = blockIdx.x >> 3, chunk = blockIdx.x & 7;
    size_t gb = (size_t)seg * NTOK + (size_t)chunk * CHUNK;
    int base = chunk * CHUNK;
    for (int i = threadIdx.x; i < CHUNK; i += 512) s[i] = g_keys[gb + i];
    __syncthreads();
    for (int k = 2; k <= CHUNK; k <<= 1) {
        for (int j = k >> 1; j > 0; j >>= 1) {
            for (int t = threadIdx.x; t < CHUNK / 2; t += 512) {
                int i = ((t & ~(j - 1)) << 1) | (t & (j - 1));
                int gi = base + i;
                bool asc = ((gi & k) == 0);
                unsigned long long a = s[i], b = s[i | j];
                if ((a > b) == asc) { s[i] = b; s[i | j] = a; }
            }
            __syncthreads();
        }
    }
    for (int i = threadIdx.x; i < CHUNK; i += 512) g_keys[gb + i] = s[i];
}

// ---------- bitonic sort: global strided pass (j >= 4096) ----------
__global__ void __launch_bounds__(256) k_gpass(int k, int j) {
    int t = blockIdx.x * 256 + threadIdx.x;
    int seg = t >> 14;       // 16384 pairs / segment
    int t2 = t & 16383;
    int i = ((t2 & ~(j - 1)) << 1) | (t2 & (j - 1));
    bool asc = ((i & k) == 0);
    size_t bs = (size_t)seg * NTOK;
    unsigned long long a = g_keys[bs + i], b = g_keys[bs + (i | j)];
    if ((a > b) == asc) { g_keys[bs + i] = b; g_keys[bs + (i | j)] = a; }
}

// ---------- bitonic sort: in-chunk finish (j = 2048..1) for stage k ----------
__global__ void __launch_bounds__(512) k_finish(int k) {
    __shared__ unsigned long long s[CHUNK];
    int seg = blockIdx.x >> 3, chunk = blockIdx.x & 7;
    size_t gb = (size_t)seg * NTOK + (size_t)chunk * CHUNK;
    int base = chunk * CHUNK;
    for (int i = threadIdx.x; i < CHUNK; i += 512) s[i] = g_keys[gb + i];
    __syncthreads();
    bool asc = ((base & k) == 0);  // uniform: k >= 8192 > CHUNK
    for (int j = CHUNK >> 1; j > 0; j >>= 1) {
        for (int t = threadIdx.x; t < CHUNK / 2; t += 512) {
            int i = ((t & ~(j - 1)) << 1) | (t & (j - 1));
            unsigned long long a = s[i], b = s[i | j];
            if ((a > b) == asc) { s[i] = b; s[i | j] = a; }
        }
        __syncthreads();
    }
    for (int i = threadIdx.x; i < CHUNK; i += 512) g_keys[gb + i] = s[i];
}

// ---------- block attention: 128x128, K=28 logits, softmax, PV ----------
__global__ void __launch_bounds__(256) k_attn() {
    __shared__ float SP[11008];                // 44032 B
    float* qs = SP;                            // 128 rows, stride 29
    float* ks = SP + 3712;                     // stride 29
    float* vs = SP + 7424;                     // 128 rows, stride 26
    int* qidx = (int*)(SP + 10752);            // 128
    int* kidx = (int*)(SP + 10880);            // 128
    float* pbuf = SP;                          // overlays qs after logits; stride 17

    int tid = threadIdx.x;
    int b = blockIdx.x, h = blockIdx.y, r = blockIdx.z;
    int seg = r * 8 + h;

    if (tid < 128)
        qidx[tid] = (int)(g_keys[(size_t)seg * NTOK + b * 128 + tid] & 0xffffffffu);
    else {
        int t = tid - 128;
        kidx[t] = (int)(g_keys[(size_t)(24 + seg) * NTOK + b * 128 + t] & 0xffffffffu);
    }
    __syncthreads();
    for (int i = tid; i < 128 * 28; i += 256) {
        int row = i / 28, kk = i - row * 28;
        qs[row * 29 + kk] = g_qhat[((size_t)h * NTOK + qidx[row]) * HDIM + kk];
        ks[row * 29 + kk] = g_khat[((size_t)h * NTOK + kidx[row]) * HDIM + kk];
    }
    for (int i = tid; i < 128 * 24; i += 256) {
        int row = i / 24, kk = i - row * 24;
        vs[row * 26 + kk] = g_qkv[(size_t)kidx[row] * 576 + 384 + h * 24 + kk];
    }
    __syncthreads();

    int ty = tid >> 4, tx = tid & 15;
    int R0 = ty * 8;
    float acc[8][8];
    #pragma unroll
    for (int a = 0; a < 8; a++)
        #pragma unroll
        for (int c = 0; c < 8; c++) acc[a][c] = 0.f;

    for (int kk = 0; kk < 28; kk++) {
        float qv[8], kv[8];
        #pragma unroll
        for (int rr = 0; rr < 8; rr++) qv[rr] = qs[(R0 + rr) * 29 + kk];
        #pragma unroll
        for (int c = 0; c < 8; c++) kv[c] = ks[(tx + 16 * c) * 29 + kk];
        #pragma unroll
        for (int rr = 0; rr < 8; rr++)
            #pragma unroll
            for (int c = 0; c < 8; c++) acc[rr][c] = fmaf(qv[rr], kv[c], acc[rr][c]);
    }

    // row softmax (16 lanes per row-group), normalize in-place, write logsumexp
    #pragma unroll
    for (int rr = 0; rr < 8; rr++) {
        float m = acc[rr][0];
        #pragma unroll
        for (int c = 1; c < 8; c++) m = fmaxf(m, acc[rr][c]);
        #pragma unroll
        for (int s = 1; s < 16; s <<= 1) m = fmaxf(m, __shfl_xor_sync(0xffffffffu, m, s));
        float sum = 0.f;
        #pragma unroll
        for (int c = 0; c < 8; c++) { acc[rr][c] = __expf(acc[rr][c] - m); sum += acc[rr][c]; }
        #pragma unroll
        for (int s = 1; s < 16; s <<= 1) sum += __shfl_xor_sync(0xffffffffu, sum, s);
        float inv = 1.f / sum;
        #pragma unroll
        for (int c = 0; c < 8; c++) acc[rr][c] *= inv;
        if (tx == 0) g_z[(size_t)seg * NTOK + qidx[R0 + rr]] = logf(sum) + m;
    }

    // PV: 8 slabs of 16 columns through pbuf (overlays qs)
    int rown = tid & 63;
    int dg = tid >> 6;                 // 4 groups x 6 dims
    int rn0 = rown * 2;
    float oa0[6], oa1[6];
    #pragma unroll
    for (int d = 0; d < 6; d++) { oa0[d] = 0.f; oa1[d] = 0.f; }

    for (int cc = 0; cc < 8; cc++) {
        __syncthreads();
        #pragma unroll
        for (int rr = 0; rr < 8; rr++) pbuf[(R0 + rr) * 17 + tx] = acc[rr][cc];
        __syncthreads();
        #pragma unroll
        for (int c16 = 0; c16 < 16; c16++) {
            float p0 = pbuf[rn0 * 17 + c16];
            float p1 = pbuf[(rn0 + 1) * 17 + c16];
            const float* vv = &vs[(c16 + 16 * cc) * 26 + dg * 6];
            #pragma unroll
            for (int d = 0; d < 6; d++) {
                float v = vv[d];
                oa0[d] = fmaf(p0, v, oa0[d]);
                oa1[d] = fmaf(p1, v, oa1[d]);
            }
        }
    }
    float* o0 = &g_o[((size_t)seg * NTOK + qidx[rn0]) * 24 + dg * 6];
    float* o1 = &g_o[((size_t)seg * NTOK + qidx[rn0 + 1]) * 24 + dg * 6];
    #pragma unroll
    for (int d = 0; d < 6; d++) { o0[d] = oa0[d]; o1[d] = oa1[d]; }
}

// ---------- combine hashes + Wo + residual + LN2 + FF + residual ----------
__global__ void __launch_bounds__(256) k_combine(
    const float* __restrict__ x, const float* __restrict__ Wo, const float* __restrict__ bo,
    const float* __restrict__ g2, const float* __restrict__ b2v,
    const float* __restrict__ W1, const float* __restrict__ b1v,
    const float* __restrict__ W2, const float* __restrict__ b2f,
    float* __restrict__ out) {
    int warp = threadIdx.x >> 5, lane = threadIdx.x & 31;
    int row = blockIdx.x * 8 + warp;
    __shared__ float outs[8][192];
    __shared__ float wsm[8][24];
    __shared__ float hsm[8][24];
    __shared__ float fsm[8][24];

    if (lane < 8) {
        int h = lane;
        float z0 = g_z[(size_t)h * NTOK + row];
        float z1 = g_z[(size_t)(8 + h) * NTOK + row];
        float z2 = g_z[(size_t)(16 + h) * NTOK + row];
        float m = fmaxf(z0, fmaxf(z1, z2));
        float e0 = __expf(z0 - m), e1 = __expf(z1 - m), e2 = __expf(z2 - m);
        float inv = 1.f / (e0 + e1 + e2);
        wsm[warp][h * 3 + 0] = e0 * inv;
        wsm[warp][h * 3 + 1] = e1 * inv;
        wsm[warp][h * 3 + 2] = e2 * inv;
    }
    __syncwarp();
    #pragma unroll
    for (int u = 0; u < 6; u++) {
        int j = lane * 6 + u;
        int h = j / 24, d = j - h * 24;
        float a = 0.f;
        #pragma unroll
        for (int r = 0; r < 3; r++)
            a = fmaf(wsm[warp][h * 3 + r], g_o[((size_t)(r * 8 + h) * NTOK + row) * 24 + d], a);
        outs[warp][j] = a;
    }
    __syncwarp();
    float xv = 0.f;
    if (lane < 24) {
        float a = bo[lane];
        for (int j = 0; j < 192; j++) a = fmaf(outs[warp][j], Wo[j * 24 + lane], a);
        xv = x[(size_t)row * 24 + lane] + a;
    }
    float s = (lane < 24) ? xv : 0.f;
    #pragma unroll
    for (int t = 16; t > 0; t >>= 1) s += __shfl_xor_sync(0xffffffffu, s, t);
    float mu = s * (1.f / 24.f);
    float dv = (lane < 24) ? (xv - mu) : 0.f;
    float v2 = dv * dv;
    #pragma unroll
    for (int t = 16; t > 0; t >>= 1) v2 += __shfl_xor_sync(0xffffffffu, v2, t);
    float inv = rsqrtf(v2 * (1.f / 24.f) + 1e-5f);
    if (lane < 24) hsm[warp][lane] = dv * inv * g2[lane] + b2v[lane];
    __syncwarp();
    if (lane < 24) {
        float f = b1v[lane];
        #pragma unroll
        for (int j = 0; j < 24; j++) f = fmaf(hsm[warp][j], W1[j * 24 + lane], f);
        fsm[warp][lane] = fmaxf(f, 0.f);
    }
    __syncwarp();
    if (lane < 24) {
        float f = b2f[lane];
        #pragma unroll
        for (int j = 0; j < 24; j++) f = fmaf(fsm[warp][j], W2[j * 24 + lane], f);
        out[(size_t)row * 24 + lane] = xv + f;
    }
}

extern "C" void kernel_launch(void* const* d_in, const int* in_sizes, int n_in,
                              void* d_out, int out_size) {
    const float* x      = (const float*)d_in[0];
    const float* coords = (const float*)d_in[1];
    const float* n1g    = (const float*)d_in[2];
    const float* n1b    = (const float*)d_in[3];
    const float* Wq     = (const float*)d_in[4];
    const float* Wk     = (const float*)d_in[5];
    const float* Wv     = (const float*)d_in[6];
    const float* wrpe   = (const float*)d_in[7];
    const float* Wo     = (const float*)d_in[8];
    const float* bo     = (const float*)d_in[9];
    const float* n2g    = (const float*)d_in[10];
    const float* n2b    = (const float*)d_in[11];
    const float* W1     = (const float*)d_in[12];
    const float* b1     = (const float*)d_in[13];
    const float* W2     = (const float*)d_in[14];
    const float* b2     = (const float*)d_in[15];
    const float* alphas = (const float*)d_in[16];
    float* out = (float*)d_out;

    k_w<<<1, 32>>>(wrpe);
    k_ln_qkv<<<NTOK / 32, 256>>>(x, n1g, n1b, Wq, Wk, Wv);
    k_build<<<(NTOK * NH) / 256, 256>>>(coords, alphas);

    k_presort<<<NSEG * 8, 512>>>();
    k_gpass<<<3072, 256>>>(8192, 4096);
    k_finish<<<NSEG * 8, 512>>>(8192);
    k_gpass<<<3072, 256>>>(16384, 8192);
    k_gpass<<<3072, 256>>>(16384, 4096);
    k_finish<<<NSEG * 8, 512>>>(16384);
    k_gpass<<<3072, 256>>>(32768, 16384);
    k_gpass<<<3072, 256>>>(32768, 8192);
    k_gpass<<<3072, 256>>>(32768, 4096);
    k_finish<<<NSEG * 8, 512>>>(32768);

    dim3 ag(NTOK / 128, NH, 3);
    k_attn<<<ag, 256>>>();
    k_combine<<<NTOK / 8, 256>>>(x, Wo, bo, n2g, n2b, W1, b1, W2, b2, out);
}

// round 3
// speedup vs baseline: 1.1709x; 1.1709x over previous
#include <cuda_runtime.h>
#include <math.h>

#define NTOK 32768
#define NH 8
#define HD 24
#define HDIM 28
#define NSEG 48
#define CHUNK 4096

// ---------- scratch (device globals; no runtime allocation) ----------
static __device__ float g_qkv[(size_t)NTOK * 576];                 // [n][q(192)|k(192)|v(192)]
static __device__ float g_qhat[(size_t)NH * NTOK * HDIM];          // [h][n][28]
static __device__ float g_khat[(size_t)NH * NTOK * HDIM];
static __device__ unsigned long long g_keys[(size_t)NSEG * NTOK];  // seg 0..23 = q(r,h), 24..47 = k(r,h)
static __device__ float g_o[(size_t)24 * NTOK * HD];               // [r*8+h][n][24] scattered to orig n
static __device__ float g_z[(size_t)24 * NTOK];                    // logsumexp, scattered
static __device__ float g_w[16];                                   // w[h][c]
static __device__ float g_wsq[16];                                 // sqrt(2*w)

__device__ __forceinline__ unsigned ford(float f) {
    unsigned u = __float_as_uint(f);
    return (u & 0x80000000u) ? ~u : (u | 0x80000000u);
}

__device__ __forceinline__ void cswap(unsigned long long& a, unsigned long long& b, bool asc) {
    if ((a > b) == asc) { unsigned long long t = a; a = b; b = t; }
}

// in-register bitonic passes j = min(K/2,4)..1 over 8 elements at global base g0
template <int K>
__device__ __forceinline__ void reg_tail(unsigned long long e[8], int g0) {
    #pragma unroll
    for (int j = (K > 8 ? 4 : K / 2); j > 0; j >>= 1) {
        #pragma unroll
        for (int r = 0; r < 8; r++) {
            if (!(r & j)) {
                bool asc = (((g0 + r) & K) == 0);
                cswap(e[r], e[r | j], asc);
            }
        }
    }
}

// ---------- RPE weights ----------
__global__ void k_w(const float* __restrict__ W) {
    int t = threadIdx.x;
    if (t < 16) {
        int h = t >> 1, c = t & 1;
        float s = 0.f;
        for (int i = 0; i < 24; i++)
            for (int j = 0; j < 8; j++)
                s += W[(h * 24 + i) * 16 + c * 8 + j];
        s *= (1.f / 192.f);
        float w = s * s;
        g_w[t] = w;
        g_wsq[t] = sqrtf(2.f * w);
    }
}

// ---------- LayerNorm1 + QKV GEMM (W-stationary: one output column per thread) ----------
__global__ void __launch_bounds__(576) k_ln_qkv(
    const float* __restrict__ x, const float* __restrict__ g1, const float* __restrict__ b1,
    const float* __restrict__ Wq, const float* __restrict__ Wk, const float* __restrict__ Wv) {
    __shared__ float xn[64][25];
    int base = blockIdx.x * 64;
    int tid = threadIdx.x;
    if (tid < 64) {
        int row = base + tid;
        float xv[24];
        float mu = 0.f;
        #pragma unroll
        for (int i = 0; i < 24; i++) { xv[i] = x[(size_t)row * 24 + i]; mu += xv[i]; }
        mu *= (1.f / 24.f);
        float var = 0.f;
        #pragma unroll
        for (int i = 0; i < 24; i++) { float d = xv[i] - mu; var += d * d; }
        var *= (1.f / 24.f);
        float inv = rsqrtf(var + 1e-5f);
        #pragma unroll
        for (int i = 0; i < 24; i++) xn[tid][i] = (xv[i] - mu) * inv * g1[i] + b1[i];
    }
    __syncthreads();
    int col = tid;
    const float* W;
    int cc;
    if (col < 192)      { W = Wq; cc = col; }
    else if (col < 384) { W = Wk; cc = col - 192; }
    else                { W = Wv; cc = col - 384; }
    float w[24];
    #pragma unroll
    for (int i = 0; i < 24; i++) w[i] = W[i * 192 + cc];
    #pragma unroll 4
    for (int row = 0; row < 64; row++) {
        float a = 0.f;
        #pragma unroll
        for (int i = 0; i < 24; i++) a = fmaf(xn[row][i], w[i], a);
        g_qkv[(size_t)(base + row) * 576 + col] = a;
    }
}

// ---------- build q_hat / k_hat + hash sort keys ----------
__global__ void __launch_bounds__(256) k_build(const float* __restrict__ coords,
                                               const float* __restrict__ alphas) {
    int idx = blockIdx.x * 256 + threadIdx.x;
    int h = idx & 7;
    int n = idx >> 3;
    float p0 = coords[n * 3 + 1], p1 = coords[n * 3 + 2];
    float sqn = g_w[h * 2] * p0 * p0 + g_w[h * 2 + 1] * p1 * p1;
    float qp0 = g_wsq[h * 2] * p0, qp1 = g_wsq[h * 2 + 1] * p1;
    float qh[HDIM], kh[HDIM];
    const float* qkv = &g_qkv[(size_t)n * 576];
    const float qscale = 0.2041241452319315f;  // 1/sqrt(24)
    #pragma unroll
    for (int i = 0; i < 24; i++) { qh[i] = qkv[h * 24 + i] * qscale; kh[i] = qkv[192 + h * 24 + i]; }
    qh[24] = qp0; qh[25] = qp1; qh[26] = -sqn; qh[27] = 1.f;
    kh[24] = qp0; kh[25] = qp1; kh[26] = 1.f;  kh[27] = -sqn;
    float* qd = &g_qhat[((size_t)h * NTOK + n) * HDIM];
    float* kd = &g_khat[((size_t)h * NTOK + n) * HDIM];
    #pragma unroll
    for (int i = 0; i < HDIM; i++) { qd[i] = qh[i]; kd[i] = kh[i]; }
    #pragma unroll
    for (int r = 0; r < 3; r++) {
        const float* a = &alphas[(r * 8 + h) * HDIM];
        float sq = 0.f, sk = 0.f;
        #pragma unroll
        for (int i = 0; i < HDIM; i++) { sq = fmaf(qh[i], a[i], sq); sk = fmaf(kh[i], a[i], sk); }
        g_keys[(size_t)(r * 8 + h) * NTOK + n] = ((unsigned long long)ford(sq) << 32) | (unsigned)n;
        g_keys[(size_t)(24 + r * 8 + h) * NTOK + n] = ((unsigned long long)ford(sk) << 32) | (unsigned)n;
    }
}

// ---------- bitonic sort: chunk presort (stages k=2..4096), register-blocked ----------
__global__ void __launch_bounds__(512) k_presort() {
    __shared__ unsigned long long s[CHUNK];
    int seg = blockIdx.x >> 3, chunk = blockIdx.x & 7;
    size_t gb = (size_t)seg * NTOK + (size_t)chunk * CHUNK;
    int base = chunk * CHUNK;
    int t = threadIdx.x;
    int e0 = t * 8;
    int g0 = base + e0;

    unsigned long long e[8];
    #pragma unroll
    for (int r = 0; r < 8; r++) e[r] = g_keys[gb + e0 + r];
    reg_tail<2>(e, g0);
    reg_tail<4>(e, g0);
    reg_tail<8>(e, g0);
    #pragma unroll
    for (int r = 0; r < 8; r++) s[e0 + r] = e[r];
    __syncthreads();

    for (int k = 16; k <= CHUNK; k <<= 1) {
        for (int j = k >> 1; j >= 8; j >>= 1) {
            #pragma unroll
            for (int u = 0; u < 4; u++) {
                int p = t + u * 512;
                int i = ((p & ~(j - 1)) << 1) | (p & (j - 1));
                bool asc = (((base + i) & k) == 0);
                unsigned long long a = s[i], b = s[i | j];
                if ((a > b) == asc) { s[i] = b; s[i | j] = a; }
            }
            __syncthreads();
        }
        // j = 4,2,1 in registers (direction uniform per thread since k >= 16)
        #pragma unroll
        for (int r = 0; r < 8; r++) e[r] = s[e0 + r];
        bool asc = ((g0 & k) == 0);
        #pragma unroll
        for (int r = 0; r < 4; r++) cswap(e[r], e[r + 4], asc);
        #pragma unroll
        for (int r = 0; r < 8; r++) if (!(r & 2)) cswap(e[r], e[r | 2], asc);
        #pragma unroll
        for (int r = 0; r < 8; r += 2) cswap(e[r], e[r + 1], asc);
        if (k < CHUNK) {
            #pragma unroll
            for (int r = 0; r < 8; r++) s[e0 + r] = e[r];
            __syncthreads();
        }
    }
    #pragma unroll
    for (int r = 0; r < 8; r++) g_keys[gb + e0 + r] = e[r];
}

// ---------- bitonic sort: global strided pass (j >= 4096) ----------
__global__ void __launch_bounds__(256) k_gpass(int k, int j) {
    int t = blockIdx.x * 256 + threadIdx.x;
    int seg = t >> 14;       // 16384 pairs / segment
    int t2 = t & 16383;
    int i = ((t2 & ~(j - 1)) << 1) | (t2 & (j - 1));
    bool asc = ((i & k) == 0);
    size_t bs = (size_t)seg * NTOK;
    unsigned long long a = g_keys[bs + i], b = g_keys[bs + (i | j)];
    if ((a > b) == asc) { g_keys[bs + i] = b; g_keys[bs + (i | j)] = a; }
}

// ---------- bitonic sort: in-chunk finish (j = 2048..1) for stage k, register-blocked ----------
__global__ void __launch_bounds__(512) k_finish(int k) {
    __shared__ unsigned long long s[CHUNK];
    int seg = blockIdx.x >> 3, chunk = blockIdx.x & 7;
    size_t gb = (size_t)seg * NTOK + (size_t)chunk * CHUNK;
    int base = chunk * CHUNK;
    int t = threadIdx.x;
    int e0 = t * 8;
    for (int i = t; i < CHUNK; i += 512) s[i] = g_keys[gb + i];
    __syncthreads();
    bool asc = ((base & k) == 0);  // uniform: k >= 8192 > CHUNK
    for (int j = CHUNK >> 1; j >= 8; j >>= 1) {
        #pragma unroll
        for (int u = 0; u < 4; u++) {
            int p = t + u * 512;
            int i = ((p & ~(j - 1)) << 1) | (p & (j - 1));
            unsigned long long a = s[i], b = s[i | j];
            if ((a > b) == asc) { s[i] = b; s[i | j] = a; }
        }
        __syncthreads();
    }
    unsigned long long e[8];
    #pragma unroll
    for (int r = 0; r < 8; r++) e[r] = s[e0 + r];
    #pragma unroll
    for (int r = 0; r < 4; r++) cswap(e[r], e[r + 4], asc);
    #pragma unroll
    for (int r = 0; r < 8; r++) if (!(r & 2)) cswap(e[r], e[r | 2], asc);
    #pragma unroll
    for (int r = 0; r < 8; r += 2) cswap(e[r], e[r + 1], asc);
    #pragma unroll
    for (int r = 0; r < 8; r++) g_keys[gb + e0 + r] = e[r];
}

// ---------- block attention: 128x128, K=28 logits, softmax, PV ----------
__global__ void __launch_bounds__(256) k_attn() {
    __shared__ float SP[11264];                // 45056 B
    float* qs = SP;                            // 128 rows, stride 30
    float* ks = SP + 3840;                     // stride 30
    float* vs = SP + 7680;                     // 128 rows, stride 26
    int* qidx = (int*)(SP + 11008);            // 128
    int* kidx = (int*)(SP + 11136);            // 128
    float* pbuf = SP;                          // overlays qs/ks after QK; [col][row], stride 132

    int tid = threadIdx.x;
    int b = blockIdx.x, h = blockIdx.y, r = blockIdx.z;
    int seg = r * 8 + h;

    if (tid < 128)
        qidx[tid] = (int)(g_keys[(size_t)seg * NTOK + b * 128 + tid] & 0xffffffffu);
    else {
        int t = tid - 128;
        kidx[t] = (int)(g_keys[(size_t)(24 + seg) * NTOK + b * 128 + t] & 0xffffffffu);
    }
    __syncthreads();
    for (int i = tid; i < 128 * 28; i += 256) {
        int row = i / 28, kk = i - row * 28;
        qs[row * 30 + kk] = g_qhat[((size_t)h * NTOK + qidx[row]) * HDIM + kk];
        ks[row * 30 + kk] = g_khat[((size_t)h * NTOK + kidx[row]) * HDIM + kk];
    }
    for (int i = tid; i < 128 * 24; i += 256) {
        int row = i / 24, kk = i - row * 24;
        vs[row * 26 + kk] = g_qkv[(size_t)kidx[row] * 576 + 384 + h * 24 + kk];
    }
    __syncthreads();

    int ty = tid >> 4, tx = tid & 15;
    int R0 = ty * 8;
    float acc[8][8];
    #pragma unroll
    for (int a = 0; a < 8; a++)
        #pragma unroll
        for (int c = 0; c < 8; c++) acc[a][c] = 0.f;

    #pragma unroll 2
    for (int kk2 = 0; kk2 < 14; kk2++) {
        float2 qv[8], kv[8];
        #pragma unroll
        for (int rr = 0; rr < 8; rr++) qv[rr] = *(const float2*)&qs[(R0 + rr) * 30 + kk2 * 2];
        #pragma unroll
        for (int c = 0; c < 8; c++) kv[c] = *(const float2*)&ks[(tx + 16 * c) * 30 + kk2 * 2];
        #pragma unroll
        for (int rr = 0; rr < 8; rr++)
            #pragma unroll
            for (int c = 0; c < 8; c++) {
                acc[rr][c] = fmaf(qv[rr].x, kv[c].x, acc[rr][c]);
                acc[rr][c] = fmaf(qv[rr].y, kv[c].y, acc[rr][c]);
            }
    }

    // row softmax (16 lanes per row-group), normalize in-place, write logsumexp
    #pragma unroll
    for (int rr = 0; rr < 8; rr++) {
        float m = acc[rr][0];
        #pragma unroll
        for (int c = 1; c < 8; c++) m = fmaxf(m, acc[rr][c]);
        #pragma unroll
        for (int s = 1; s < 16; s <<= 1) m = fmaxf(m, __shfl_xor_sync(0xffffffffu, m, s));
        float sum = 0.f;
        #pragma unroll
        for (int c = 0; c < 8; c++) { acc[rr][c] = __expf(acc[rr][c] - m); sum += acc[rr][c]; }
        #pragma unroll
        for (int s = 1; s < 16; s <<= 1) sum += __shfl_xor_sync(0xffffffffu, sum, s);
        float inv = 1.f / sum;
        #pragma unroll
        for (int c = 0; c < 8; c++) acc[rr][c] *= inv;
        if (tx == 0) g_z[(size_t)seg * NTOK + qidx[R0 + rr]] = logf(sum) + m;
    }

    // PV: 4 rounds of 32 columns through transposed pbuf [col][row]
    int rown = tid & 63;
    int dg = tid >> 6;                 // 4 groups x 6 dims
    int rn0 = rown * 2;
    float oa0[6], oa1[6];
    #pragma unroll
    for (int d = 0; d < 6; d++) { oa0[d] = 0.f; oa1[d] = 0.f; }

    for (int round = 0; round < 4; round++) {
        __syncthreads();
        #pragma unroll
        for (int cc2 = 0; cc2 < 2; cc2++) {
            int cc = round * 2 + cc2;
            int lc = tx + 16 * cc2;
            #pragma unroll
            for (int rr = 0; rr < 8; rr++) pbuf[lc * 132 + R0 + rr] = acc[rr][cc];
        }
        __syncthreads();
        #pragma unroll 4
        for (int c16 = 0; c16 < 32; c16++) {
            float2 p = *(const float2*)&pbuf[c16 * 132 + rn0];
            int gcol = round * 32 + c16;
            const float2* vv = (const float2*)&vs[gcol * 26 + dg * 6];
            float2 v0 = vv[0], v1 = vv[1], v2 = vv[2];
            oa0[0] = fmaf(p.x, v0.x, oa0[0]); oa1[0] = fmaf(p.y, v0.x, oa1[0]);
            oa0[1] = fmaf(p.x, v0.y, oa0[1]); oa1[1] = fmaf(p.y, v0.y, oa1[1]);
            oa0[2] = fmaf(p.x, v1.x, oa0[2]); oa1[2] = fmaf(p.y, v1.x, oa1[2]);
            oa0[3] = fmaf(p.x, v1.y, oa0[3]); oa1[3] = fmaf(p.y, v1.y, oa1[3]);
            oa0[4] = fmaf(p.x, v2.x, oa0[4]); oa1[4] = fmaf(p.y, v2.x, oa1[4]);
            oa0[5] = fmaf(p.x, v2.y, oa0[5]); oa1[5] = fmaf(p.y, v2.y, oa1[5]);
        }
    }
    float* o0 = &g_o[((size_t)seg * NTOK + qidx[rn0]) * 24 + dg * 6];
    float* o1 = &g_o[((size_t)seg * NTOK + qidx[rn0 + 1]) * 24 + dg * 6];
    #pragma unroll
    for (int d = 0; d < 6; d++) { o0[d] = oa0[d]; o1[d] = oa1[d]; }
}

// ---------- combine hashes + Wo + residual + LN2 + FF + residual ----------
__global__ void __launch_bounds__(512) k_combine(
    const float* __restrict__ x, const float* __restrict__ Wo, const float* __restrict__ bo,
    const float* __restrict__ g2, const float* __restrict__ b2v,
    const float* __restrict__ W1, const float* __restrict__ b1v,
    const float* __restrict__ W2, const float* __restrict__ b2f,
    float* __restrict__ out) {
    __shared__ float Wo_s[4608];
    __shared__ float outs[16][192];
    __shared__ float wsm[16][24];
    __shared__ float hsm[16][24];
    __shared__ float fsm[16][24];
    int warp = threadIdx.x >> 5, lane = threadIdx.x & 31;
    int row = blockIdx.x * 16 + warp;

    for (int i = threadIdx.x; i < 4608; i += 512) Wo_s[i] = Wo[i];
    __syncthreads();

    if (lane < 8) {
        int h = lane;
        float z0 = g_z[(size_t)h * NTOK + row];
        float z1 = g_z[(size_t)(8 + h) * NTOK + row];
        float z2 = g_z[(size_t)(16 + h) * NTOK + row];
        float m = fmaxf(z0, fmaxf(z1, z2));
        float e0 = __expf(z0 - m), e1 = __expf(z1 - m), e2 = __expf(z2 - m);
        float inv = 1.f / (e0 + e1 + e2);
        wsm[warp][h * 3 + 0] = e0 * inv;
        wsm[warp][h * 3 + 1] = e1 * inv;
        wsm[warp][h * 3 + 2] = e2 * inv;
    }
    __syncwarp();
    #pragma unroll
    for (int u = 0; u < 6; u++) {
        int j = lane * 6 + u;
        int h = j / 24, d = j - h * 24;
        float a = 0.f;
        #pragma unroll
        for (int r = 0; r < 3; r++)
            a = fmaf(wsm[warp][h * 3 + r], g_o[((size_t)(r * 8 + h) * NTOK + row) * 24 + d], a);
        outs[warp][j] = a;
    }
    __syncwarp();
    float xv = 0.f;
    if (lane < 24) {
        float a = bo[lane];
        #pragma unroll 4
        for (int j = 0; j < 192; j++) a = fmaf(outs[warp][j], Wo_s[j * 24 + lane], a);
        xv = x[(size_t)row * 24 + lane] + a;
    }
    float s = (lane < 24) ? xv : 0.f;
    #pragma unroll
    for (int t = 16; t > 0; t >>= 1) s += __shfl_xor_sync(0xffffffffu, s, t);
    float mu = s * (1.f / 24.f);
    float dv = (lane < 24) ? (xv - mu) : 0.f;
    float v2 = dv * dv;
    #pragma unroll
    for (int t = 16; t > 0; t >>= 1) v2 += __shfl_xor_sync(0xffffffffu, v2, t);
    float inv = rsqrtf(v2 * (1.f / 24.f) + 1e-5f);
    if (lane < 24) hsm[warp][lane] = dv * inv * g2[lane] + b2v[lane];
    __syncwarp();
    if (lane < 24) {
        float f = b1v[lane];
        #pragma unroll
        for (int j = 0; j < 24; j++) f = fmaf(hsm[warp][j], W1[j * 24 + lane], f);
        fsm[warp][lane] = fmaxf(f, 0.f);
    }
    __syncwarp();
    if (lane < 24) {
        float f = b2f[lane];
        #pragma unroll
        for (int j = 0; j < 24; j++) f = fmaf(fsm[warp][j], W2[j * 24 + lane], f);
        out[(size_t)row * 24 + lane] = xv + f;
    }
}

extern "C" void kernel_launch(void* const* d_in, const int* in_sizes, int n_in,
                              void* d_out, int out_size) {
    const float* x      = (const float*)d_in[0];
    const float* coords = (const float*)d_in[1];
    const float* n1g    = (const float*)d_in[2];
    const float* n1b    = (const float*)d_in[3];
    const float* Wq     = (const float*)d_in[4];
    const float* Wk     = (const float*)d_in[5];
    const float* Wv     = (const float*)d_in[6];
    const float* wrpe   = (const float*)d_in[7];
    const float* Wo     = (const float*)d_in[8];
    const float* bo     = (const float*)d_in[9];
    const float* n2g    = (const float*)d_in[10];
    const float* n2b    = (const float*)d_in[11];
    const float* W1     = (const float*)d_in[12];
    const float* b1     = (const float*)d_in[13];
    const float* W2     = (const float*)d_in[14];
    const float* b2     = (const float*)d_in[15];
    const float* alphas = (const float*)d_in[16];
    float* out = (float*)d_out;

    k_w<<<1, 32>>>(wrpe);
    k_ln_qkv<<<NTOK / 64, 576>>>(x, n1g, n1b, Wq, Wk, Wv);
    k_build<<<(NTOK * NH) / 256, 256>>>(coords, alphas);

    k_presort<<<NSEG * 8, 512>>>();
    k_gpass<<<3072, 256>>>(8192, 4096);
    k_finish<<<NSEG * 8, 512>>>(8192);
    k_gpass<<<3072, 256>>>(16384, 8192);
    k_gpass<<<3072, 256>>>(16384, 4096);
    k_finish<<<NSEG * 8, 512>>>(16384);
    k_gpass<<<3072, 256>>>(32768, 16384);
    k_gpass<<<3072, 256>>>(32768, 8192);
    k_gpass<<<3072, 256>>>(32768, 4096);
    k_finish<<<NSEG * 8, 512>>>(32768);

    dim3 ag(NTOK / 128, NH, 3);
    k_attn<<<ag, 256>>>();
    k_combine<<<NTOK / 16, 512>>>(x, Wo, bo, n2g, n2b, W1, b1, W2, b2, out);
}

// round 4
// speedup vs baseline: 1.2247x; 1.0460x over previous
#include <cuda_runtime.h>
#include <math.h>

#define NTOK 32768
#define NH 8
#define HD 24
#define HDIM 28
#define NSEG 48
#define CHUNK 4096

typedef unsigned long long ull;

// ---------- packed fp32 helpers (sm_103a f32x2) ----------
#define FMA_F32X2(d, a, b, c) \
    asm("fma.rn.f32x2 %0, %1, %2, %3;" : "=l"(d) : "l"(a), "l"(b), "l"(c))
#define PACK_F32X2(out, lo, hi) \
    asm("mov.b64 %0, {%1, %2};" : "=l"(out) : "r"(lo), "r"(hi))
#define UNPACK_F32X2(lo, hi, in) \
    asm("mov.b64 {%0, %1}, %2;" : "=r"(lo), "=r"(hi) : "l"(in))

// bank-deswizzle for u64 shared arrays in bitonic passes
#define PHYS(i) ((i) ^ ((((i) >> 4) & 1) << 3))

// ---------- scratch (device globals; no runtime allocation) ----------
static __device__ float g_qkv[(size_t)NTOK * 576];                 // [n][q|k|v]
static __device__ float g_qhat[(size_t)NH * NTOK * HDIM];
static __device__ float g_khat[(size_t)NH * NTOK * HDIM];
static __device__ ull   g_keys[(size_t)NSEG * NTOK];
static __device__ float g_o[(size_t)24 * NTOK * HD];
static __device__ float g_z[(size_t)24 * NTOK];
static __device__ float g_w[16];
static __device__ float g_wsq[16];

__device__ __forceinline__ unsigned ford(float f) {
    unsigned u = __float_as_uint(f);
    return (u & 0x80000000u) ? ~u : (u | 0x80000000u);
}

__device__ __forceinline__ void cswap(ull& a, ull& b, bool asc) {
    if ((a > b) == asc) { ull t = a; a = b; b = t; }
}

template <int K>
__device__ __forceinline__ void reg_tail(ull e[8], int g0) {
    #pragma unroll
    for (int j = (K > 8 ? 4 : K / 2); j > 0; j >>= 1) {
        #pragma unroll
        for (int r = 0; r < 8; r++) {
            if (!(r & j)) {
                bool asc = (((g0 + r) & K) == 0);
                cswap(e[r], e[r | j], asc);
            }
        }
    }
}

// ---------- RPE weights ----------
__global__ void k_w(const float* __restrict__ W) {
    int t = threadIdx.x;
    if (t < 16) {
        int h = t >> 1, c = t & 1;
        float s = 0.f;
        for (int i = 0; i < 24; i++)
            for (int j = 0; j < 8; j++)
                s += W[(h * 24 + i) * 16 + c * 8 + j];
        s *= (1.f / 192.f);
        float w = s * s;
        g_w[t] = w;
        g_wsq[t] = sqrtf(2.f * w);
    }
}

// ---------- LayerNorm1 + QKV GEMM (W-stationary) ----------
__global__ void __launch_bounds__(576) k_ln_qkv(
    const float* __restrict__ x, const float* __restrict__ g1, const float* __restrict__ b1,
    const float* __restrict__ Wq, const float* __restrict__ Wk, const float* __restrict__ Wv) {
    __shared__ float xn[64][25];
    int base = blockIdx.x * 64;
    int tid = threadIdx.x;
    if (tid < 64) {
        int row = base + tid;
        float xv[24];
        float mu = 0.f;
        #pragma unroll
        for (int i = 0; i < 24; i++) { xv[i] = x[(size_t)row * 24 + i]; mu += xv[i]; }
        mu *= (1.f / 24.f);
        float var = 0.f;
        #pragma unroll
        for (int i = 0; i < 24; i++) { float d = xv[i] - mu; var += d * d; }
        var *= (1.f / 24.f);
        float inv = rsqrtf(var + 1e-5f);
        #pragma unroll
        for (int i = 0; i < 24; i++) xn[tid][i] = (xv[i] - mu) * inv * g1[i] + b1[i];
    }
    __syncthreads();
    int col = tid;
    const float* W;
    int cc;
    if (col < 192)      { W = Wq; cc = col; }
    else if (col < 384) { W = Wk; cc = col - 192; }
    else                { W = Wv; cc = col - 384; }
    float w[24];
    #pragma unroll
    for (int i = 0; i < 24; i++) w[i] = W[i * 192 + cc];
    #pragma unroll 4
    for (int row = 0; row < 64; row++) {
        float a = 0.f;
        #pragma unroll
        for (int i = 0; i < 24; i++) a = fmaf(xn[row][i], w[i], a);
        g_qkv[(size_t)(base + row) * 576 + col] = a;
    }
}

// ---------- build q_hat / k_hat + hash sort keys ----------
__global__ void __launch_bounds__(256) k_build(const float* __restrict__ coords,
                                               const float* __restrict__ alphas) {
    int idx = blockIdx.x * 256 + threadIdx.x;
    int h = idx & 7;
    int n = idx >> 3;
    float p0 = coords[n * 3 + 1], p1 = coords[n * 3 + 2];
    float sqn = g_w[h * 2] * p0 * p0 + g_w[h * 2 + 1] * p1 * p1;
    float qp0 = g_wsq[h * 2] * p0, qp1 = g_wsq[h * 2 + 1] * p1;
    float qh[HDIM], kh[HDIM];
    const float* qkv = &g_qkv[(size_t)n * 576];
    const float qscale = 0.2041241452319315f;
    #pragma unroll
    for (int i = 0; i < 24; i++) { qh[i] = qkv[h * 24 + i] * qscale; kh[i] = qkv[192 + h * 24 + i]; }
    qh[24] = qp0; qh[25] = qp1; qh[26] = -sqn; qh[27] = 1.f;
    kh[24] = qp0; kh[25] = qp1; kh[26] = 1.f;  kh[27] = -sqn;
    float* qd = &g_qhat[((size_t)h * NTOK + n) * HDIM];
    float* kd = &g_khat[((size_t)h * NTOK + n) * HDIM];
    #pragma unroll
    for (int i = 0; i < HDIM; i++) { qd[i] = qh[i]; kd[i] = kh[i]; }
    #pragma unroll
    for (int r = 0; r < 3; r++) {
        const float* a = &alphas[(r * 8 + h) * HDIM];
        float sq = 0.f, sk = 0.f;
        #pragma unroll
        for (int i = 0; i < HDIM; i++) { sq = fmaf(qh[i], a[i], sq); sk = fmaf(kh[i], a[i], sk); }
        g_keys[(size_t)(r * 8 + h) * NTOK + n] = ((ull)ford(sq) << 32) | (unsigned)n;
        g_keys[(size_t)(24 + r * 8 + h) * NTOK + n] = ((ull)ford(sk) << 32) | (unsigned)n;
    }
}

// ---------- bitonic: chunk presort (k=2..4096), register-blocked + deswizzled ----------
__global__ void __launch_bounds__(512) k_presort() {
    __shared__ ull s[CHUNK];
    int seg = blockIdx.x >> 3, chunk = blockIdx.x & 7;
    size_t gb = (size_t)seg * NTOK + (size_t)chunk * CHUNK;
    int base = chunk * CHUNK;
    int t = threadIdx.x;
    int e0 = t * 8;
    int g0 = base + e0;

    ull e[8];
    #pragma unroll
    for (int r = 0; r < 8; r++) e[r] = g_keys[gb + e0 + r];
    reg_tail<2>(e, g0);
    reg_tail<4>(e, g0);
    reg_tail<8>(e, g0);
    {
        int p0 = PHYS(e0);
        #pragma unroll
        for (int r = 0; r < 8; r++) s[p0 + r] = e[r];
    }
    __syncthreads();

    for (int k = 16; k <= CHUNK; k <<= 1) {
        for (int j = k >> 1; j >= 8; j >>= 1) {
            #pragma unroll
            for (int u = 0; u < 4; u++) {
                int p = t + u * 512;
                int i = ((p & ~(j - 1)) << 1) | (p & (j - 1));
                int i2 = i | j;
                bool asc = (((base + i) & k) == 0);
                ull a = s[PHYS(i)], b = s[PHYS(i2)];
                if ((a > b) == asc) { s[PHYS(i)] = b; s[PHYS(i2)] = a; }
            }
            __syncthreads();
        }
        int p0 = PHYS(e0);
        #pragma unroll
        for (int r = 0; r < 8; r++) e[r] = s[p0 + r];
        bool asc = ((g0 & k) == 0);
        #pragma unroll
        for (int r = 0; r < 4; r++) cswap(e[r], e[r + 4], asc);
        #pragma unroll
        for (int r = 0; r < 8; r++) if (!(r & 2)) cswap(e[r], e[r | 2], asc);
        #pragma unroll
        for (int r = 0; r < 8; r += 2) cswap(e[r], e[r + 1], asc);
        if (k < CHUNK) {
            #pragma unroll
            for (int r = 0; r < 8; r++) s[p0 + r] = e[r];
            __syncthreads();
        }
    }
    #pragma unroll
    for (int r = 0; r < 8; r++) g_keys[gb + e0 + r] = e[r];
}

// ---------- fused global merge: all j in {16384,8192,4096} for stage k ----------
__global__ void __launch_bounds__(256) k_gmerge(int k) {
    int t = blockIdx.x * 256 + threadIdx.x;   // 48*4096 threads
    int seg = t >> 12;
    int g = t & 4095;
    size_t bs = (size_t)seg * NTOK;
    ull e[8];
    #pragma unroll
    for (int m = 0; m < 8; m++) e[m] = g_keys[bs + g + 4096 * m];
    #pragma unroll
    for (int j = 4; j >= 1; j >>= 1) {        // j*4096 element stride
        if (j * 8192 <= k) {
            #pragma unroll
            for (int m = 0; m < 8; m++) {
                if (!(m & j)) {
                    bool asc = (((m * 4096) & k) == 0);
                    cswap(e[m], e[m + j], asc);
                }
            }
        }
    }
    #pragma unroll
    for (int m = 0; m < 8; m++) g_keys[bs + g + 4096 * m] = e[m];
}

// ---------- bitonic: in-chunk finish (j=2048..1), register-blocked + deswizzled ----------
__global__ void __launch_bounds__(512) k_finish(int k) {
    __shared__ ull s[CHUNK];
    int seg = blockIdx.x >> 3, chunk = blockIdx.x & 7;
    size_t gb = (size_t)seg * NTOK + (size_t)chunk * CHUNK;
    int base = chunk * CHUNK;
    int t = threadIdx.x;
    int e0 = t * 8;
    for (int i = t; i < CHUNK; i += 512) s[PHYS(i)] = g_keys[gb + i];
    __syncthreads();
    bool asc = ((base & k) == 0);  // uniform: k >= 8192 > CHUNK
    for (int j = CHUNK >> 1; j >= 8; j >>= 1) {
        #pragma unroll
        for (int u = 0; u < 4; u++) {
            int p = t + u * 512;
            int i = ((p & ~(j - 1)) << 1) | (p & (j - 1));
            int i2 = i | j;
            ull a = s[PHYS(i)], b = s[PHYS(i2)];
            if ((a > b) == asc) { s[PHYS(i)] = b; s[PHYS(i2)] = a; }
        }
        __syncthreads();
    }
    ull e[8];
    int p0 = PHYS(e0);
    #pragma unroll
    for (int r = 0; r < 8; r++) e[r] = s[p0 + r];
    #pragma unroll
    for (int r = 0; r < 4; r++) cswap(e[r], e[r + 4], asc);
    #pragma unroll
    for (int r = 0; r < 8; r++) if (!(r & 2)) cswap(e[r], e[r | 2], asc);
    #pragma unroll
    for (int r = 0; r < 8; r += 2) cswap(e[r], e[r + 1], asc);
    #pragma unroll
    for (int r = 0; r < 8; r++) g_keys[gb + e0 + r] = e[r];
}

// ---------- block attention: f32x2-packed 128x128 ----------
__global__ void __launch_bounds__(256) k_attn() {
    __shared__ __align__(16) float SP[11072];  // 44288 B
    float* qs_t = SP;                          // [kk][row] 28 x 130
    float* ks   = SP + 3648;                   // [row][kk] 128 x 30
    float* vs   = SP + 7488;                   // [row][d]  128 x 26
    int* qidx = (int*)(SP + 10816);
    int* kidx = (int*)(SP + 10944);
    float* pbuf = SP;                          // overlays qs_t/ks: [col][rowpair], 32 x 134

    int tid = threadIdx.x;
    int b = blockIdx.x, h = blockIdx.y, r = blockIdx.z;
    int seg = r * 8 + h;

    if (tid < 128)
        qidx[tid] = (int)(g_keys[(size_t)seg * NTOK + b * 128 + tid] & 0xffffffffu);
    else {
        int t = tid - 128;
        kidx[t] = (int)(g_keys[(size_t)(24 + seg) * NTOK + b * 128 + t] & 0xffffffffu);
    }
    __syncthreads();
    for (int i = tid; i < 128 * 28; i += 256) {
        int row = i / 28, kk = i - row * 28;
        qs_t[kk * 130 + row] = g_qhat[((size_t)h * NTOK + qidx[row]) * HDIM + kk];
        ks[row * 30 + kk]    = g_khat[((size_t)h * NTOK + kidx[row]) * HDIM + kk];
    }
    for (int i = tid; i < 128 * 24; i += 256) {
        int row = i / 24, kk = i - row * 24;
        vs[row * 26 + kk] = g_qkv[(size_t)kidx[row] * 576 + 384 + h * 24 + kk];
    }
    __syncthreads();

    int ty = tid >> 4, tx = tid & 15;
    int R0 = ty * 8;
    ull acc2[4][8];
    #pragma unroll
    for (int u = 0; u < 4; u++)
        #pragma unroll
        for (int c = 0; c < 8; c++) acc2[u][c] = 0ULL;

    // QK: packed over row pairs; k splat on ALU pipe
    #pragma unroll 2
    for (int kk = 0; kk < 28; kk++) {
        ull qp[4];
        #pragma unroll
        for (int u = 0; u < 4; u++)
            qp[u] = *(const ull*)&qs_t[kk * 130 + R0 + 2 * u];
        #pragma unroll
        for (int c = 0; c < 8; c++) {
            float kv = ks[(tx + 16 * c) * 30 + kk];
            unsigned kb = __float_as_uint(kv);
            ull kp;
            PACK_F32X2(kp, kb, kb);
            #pragma unroll
            for (int u = 0; u < 4; u++)
                FMA_F32X2(acc2[u][c], qp[u], kp, acc2[u][c]);
        }
    }

    // unpack for softmax
    float acc[8][8];
    #pragma unroll
    for (int u = 0; u < 4; u++)
        #pragma unroll
        for (int c = 0; c < 8; c++) {
            unsigned lo, hi;
            UNPACK_F32X2(lo, hi, acc2[u][c]);
            acc[2 * u][c] = __uint_as_float(lo);
            acc[2 * u + 1][c] = __uint_as_float(hi);
        }

    #pragma unroll
    for (int rr = 0; rr < 8; rr++) {
        float m = acc[rr][0];
        #pragma unroll
        for (int c = 1; c < 8; c++) m = fmaxf(m, acc[rr][c]);
        #pragma unroll
        for (int s = 1; s < 16; s <<= 1) m = fmaxf(m, __shfl_xor_sync(0xffffffffu, m, s));
        float sum = 0.f;
        #pragma unroll
        for (int c = 0; c < 8; c++) { acc[rr][c] = __expf(acc[rr][c] - m); sum += acc[rr][c]; }
        #pragma unroll
        for (int s = 1; s < 16; s <<= 1) sum += __shfl_xor_sync(0xffffffffu, sum, s);
        float inv = 1.f / sum;
        #pragma unroll
        for (int c = 0; c < 8; c++) acc[rr][c] *= inv;
        if (tx == 0) g_z[(size_t)seg * NTOK + qidx[R0 + rr]] = logf(sum) + m;
    }

    // repack normalized P into row-pair u64s
    #pragma unroll
    for (int u = 0; u < 4; u++)
        #pragma unroll
        for (int c = 0; c < 8; c++) {
            unsigned lo = __float_as_uint(acc[2 * u][c]);
            unsigned hi = __float_as_uint(acc[2 * u + 1][c]);
            PACK_F32X2(acc2[u][c], lo, hi);
        }

    // PV: 4 rounds of 32 cols, P stored/loaded as packed row pairs
    int rown = tid & 63;
    int dg = tid >> 6;
    int rn0 = rown * 2;
    ull oap[6];
    #pragma unroll
    for (int d = 0; d < 6; d++) oap[d] = 0ULL;

    for (int round = 0; round < 4; round++) {
        __syncthreads();
        #pragma unroll
        for (int cc2 = 0; cc2 < 2; cc2++) {
            int cc = round * 2 + cc2;
            int lc = tx + 16 * cc2;
            #pragma unroll
            for (int u = 0; u < 4; u++)
                *(ull*)&pbuf[lc * 134 + R0 + 2 * u] = acc2[u][cc];
        }
        __syncthreads();
        #pragma unroll 4
        for (int c16 = 0; c16 < 32; c16++) {
            ull pp = *(const ull*)&pbuf[c16 * 134 + rn0];
            int gcol = round * 32 + c16;
            const float2* vv = (const float2*)&vs[gcol * 26 + dg * 6];
            float2 v0 = vv[0], v1 = vv[1], v2 = vv[2];
            ull vp;
            unsigned b0;
            b0 = __float_as_uint(v0.x); PACK_F32X2(vp, b0, b0); FMA_F32X2(oap[0], pp, vp, oap[0]);
            b0 = __float_as_uint(v0.y); PACK_F32X2(vp, b0, b0); FMA_F32X2(oap[1], pp, vp, oap[1]);
            b0 = __float_as_uint(v1.x); PACK_F32X2(vp, b0, b0); FMA_F32X2(oap[2], pp, vp, oap[2]);
            b0 = __float_as_uint(v1.y); PACK_F32X2(vp, b0, b0); FMA_F32X2(oap[3], pp, vp, oap[3]);
            b0 = __float_as_uint(v2.x); PACK_F32X2(vp, b0, b0); FMA_F32X2(oap[4], pp, vp, oap[4]);
            b0 = __float_as_uint(v2.y); PACK_F32X2(vp, b0, b0); FMA_F32X2(oap[5], pp, vp, oap[5]);
        }
    }
    float* o0 = &g_o[((size_t)seg * NTOK + qidx[rn0]) * 24 + dg * 6];
    float* o1 = &g_o[((size_t)seg * NTOK + qidx[rn0 + 1]) * 24 + dg * 6];
    #pragma unroll
    for (int d = 0; d < 6; d++) {
        unsigned lo, hi;
        UNPACK_F32X2(lo, hi, oap[d]);
        o0[d] = __uint_as_float(lo);
        o1[d] = __uint_as_float(hi);
    }
}

// ---------- combine hashes + Wo + residual + LN2 + FF + residual ----------
__global__ void __launch_bounds__(512) k_combine(
    const float* __restrict__ x, const float* __restrict__ Wo, const float* __restrict__ bo,
    const float* __restrict__ g2, const float* __restrict__ b2v,
    const float* __restrict__ W1, const float* __restrict__ b1v,
    const float* __restrict__ W2, const float* __restrict__ b2f,
    float* __restrict__ out) {
    __shared__ float Wo_s[4608];
    __shared__ float outs[16][192];
    __shared__ float wsm[16][24];
    __shared__ float hsm[16][24];
    __shared__ float fsm[16][24];
    int warp = threadIdx.x >> 5, lane = threadIdx.x & 31;
    int row = blockIdx.x * 16 + warp;

    for (int i = threadIdx.x; i < 4608; i += 512) Wo_s[i] = Wo[i];
    __syncthreads();

    if (lane < 8) {
        int h = lane;
        float z0 = g_z[(size_t)h * NTOK + row];
        float z1 = g_z[(size_t)(8 + h) * NTOK + row];
        float z2 = g_z[(size_t)(16 + h) * NTOK + row];
        float m = fmaxf(z0, fmaxf(z1, z2));
        float e0 = __expf(z0 - m), e1 = __expf(z1 - m), e2 = __expf(z2 - m);
        float inv = 1.f / (e0 + e1 + e2);
        wsm[warp][h * 3 + 0] = e0 * inv;
        wsm[warp][h * 3 + 1] = e1 * inv;
        wsm[warp][h * 3 + 2] = e2 * inv;
    }
    __syncwarp();
    #pragma unroll
    for (int u = 0; u < 6; u++) {
        int j = lane * 6 + u;
        int h = j / 24, d = j - h * 24;
        float a = 0.f;
        #pragma unroll
        for (int r = 0; r < 3; r++)
            a = fmaf(wsm[warp][h * 3 + r], g_o[((size_t)(r * 8 + h) * NTOK + row) * 24 + d], a);
        outs[warp][j] = a;
    }
    __syncwarp();
    float xv = 0.f;
    if (lane < 24) {
        float a = bo[lane];
        #pragma unroll 4
        for (int j = 0; j < 192; j++) a = fmaf(outs[warp][j], Wo_s[j * 24 + lane], a);
        xv = x[(size_t)row * 24 + lane] + a;
    }
    float s = (lane < 24) ? xv : 0.f;
    #pragma unroll
    for (int t = 16; t > 0; t >>= 1) s += __shfl_xor_sync(0xffffffffu, s, t);
    float mu = s * (1.f / 24.f);
    float dv = (lane < 24) ? (xv - mu) : 0.f;
    float v2 = dv * dv;
    #pragma unroll
    for (int t = 16; t > 0; t >>= 1) v2 += __shfl_xor_sync(0xffffffffu, v2, t);
    float inv = rsqrtf(v2 * (1.f / 24.f) + 1e-5f);
    if (lane < 24) hsm[warp][lane] = dv * inv * g2[lane] + b2v[lane];
    __syncwarp();
    if (lane < 24) {
        float f = b1v[lane];
        #pragma unroll
        for (int j = 0; j < 24; j++) f = fmaf(hsm[warp][j], W1[j * 24 + lane], f);
        fsm[warp][lane] = fmaxf(f, 0.f);
    }
    __syncwarp();
    if (lane < 24) {
        float f = b2f[lane];
        #pragma unroll
        for (int j = 0; j < 24; j++) f = fmaf(fsm[warp][j], W2[j * 24 + lane], f);
        out[(size_t)row * 24 + lane] = xv + f;
    }
}

extern "C" void kernel_launch(void* const* d_in, const int* in_sizes, int n_in,
                              void* d_out, int out_size) {
    const float* x      = (const float*)d_in[0];
    const float* coords = (const float*)d_in[1];
    const float* n1g    = (const float*)d_in[2];
    const float* n1b    = (const float*)d_in[3];
    const float* Wq     = (const float*)d_in[4];
    const float* Wk     = (const float*)d_in[5];
    const float* Wv     = (const float*)d_in[6];
    const float* wrpe   = (const float*)d_in[7];
    const float* Wo     = (const float*)d_in[8];
    const float* bo     = (const float*)d_in[9];
    const float* n2g    = (const float*)d_in[10];
    const float* n2b    = (const float*)d_in[11];
    const float* W1     = (const float*)d_in[12];
    const float* b1     = (const float*)d_in[13];
    const float* W2     = (const float*)d_in[14];
    const float* b2     = (const float*)d_in[15];
    const float* alphas = (const float*)d_in[16];
    float* out = (float*)d_out;

    k_w<<<1, 32>>>(wrpe);
    k_ln_qkv<<<NTOK / 64, 576>>>(x, n1g, n1b, Wq, Wk, Wv);
    k_build<<<(NTOK * NH) / 256, 256>>>(coords, alphas);

    k_presort<<<NSEG * 8, 512>>>();
    k_gmerge<<<768, 256>>>(8192);
    k_finish<<<NSEG * 8, 512>>>(8192);
    k_gmerge<<<768, 256>>>(16384);
    k_finish<<<NSEG * 8, 512>>>(16384);
    k_gmerge<<<768, 256>>>(32768);
    k_finish<<<NSEG * 8, 512>>>(32768);

    dim3 ag(NTOK / 128, NH, 3);
    k_attn<<<ag, 256>>>();
    k_combine<<<NTOK / 16, 512>>>(x, Wo, bo, n2g, n2b, W1, b1, W2, b2, out);
}